// round 12
// baseline (speedup 1.0000x reference)
#include <cuda_runtime.h>
#include <cuda_fp16.h>
#include <stdint.h>

#define NN 100000
#define GG 1024
#define HH 16
#define CAP 128   // bucket capacity per node (mean deg 32; P(>=128) ~ 1e-30)

// Scratch (device globals; no allocation allowed)
__device__ unsigned d_p0[NN];        // packed (class << 16) | fp16(dis)
__device__ uint4 d_h1[NN * 2];       // hs1 rows, fp16, 32B each
__device__ float d_t[NN];            // t[n] = hs2[n]·Wo
__device__ float d_dis[NN];
__device__ float d_cnt[GG];
__device__ int   d_deg[NN];          // degree counter (zeroed each call)
__device__ int   d_csr[(size_t)NN * CAP];

// ---------------------------------------------------------------------------
// Single edge pass: count + fill buckets. 8 edges per thread (2 int4 loads).
__global__ void k_fill(const int* __restrict__ src, const int* __restrict__ dst, int e) {
    int i = blockIdx.x * blockDim.x + threadIdx.x;
    int e8 = e >> 3;
    if (i < e8) {
        int4 da = ((const int4*)dst)[2 * i];
        int4 db = ((const int4*)dst)[2 * i + 1];
        int4 sa = ((const int4*)src)[2 * i];
        int4 sb = ((const int4*)src)[2 * i + 1];
        int p;
        p = atomicAdd(&d_deg[da.x], 1); if (p < CAP) d_csr[(size_t)da.x * CAP + p] = sa.x;
        p = atomicAdd(&d_deg[da.y], 1); if (p < CAP) d_csr[(size_t)da.y * CAP + p] = sa.y;
        p = atomicAdd(&d_deg[da.z], 1); if (p < CAP) d_csr[(size_t)da.z * CAP + p] = sa.z;
        p = atomicAdd(&d_deg[da.w], 1); if (p < CAP) d_csr[(size_t)da.w * CAP + p] = sa.w;
        p = atomicAdd(&d_deg[db.x], 1); if (p < CAP) d_csr[(size_t)db.x * CAP + p] = sb.x;
        p = atomicAdd(&d_deg[db.y], 1); if (p < CAP) d_csr[(size_t)db.y * CAP + p] = sb.y;
        p = atomicAdd(&d_deg[db.z], 1); if (p < CAP) d_csr[(size_t)db.z * CAP + p] = sb.z;
        p = atomicAdd(&d_deg[db.w], 1); if (p < CAP) d_csr[(size_t)db.w * CAP + p] = sb.w;
    } else {
        int j = e8 * 8 + (i - e8);   // scalar tail (< 8 edges)
        if (j < e) {
            int d = dst[j];
            int p = atomicAdd(&d_deg[d], 1);
            if (p < CAP) d_csr[(size_t)d * CAP + p] = src[j];
        }
    }
}

// ---------------------------------------------------------------------------
// Node prep: dis, pad zeroing, packed (class,dis), batch count, out init.
__global__ void k_node0(const int* __restrict__ batch, float* __restrict__ out,
                        const float* __restrict__ bo,
                        const int* __restrict__ types, const int* __restrict__ pos,
                        int n, int g) {
    int i = blockIdx.x * blockDim.x + threadIdx.x;
    bool active = (i < n);
    if (active) {
        int deg = d_deg[i];
        float ds = rsqrtf((float)deg + 1.0f);
        d_dis[i] = ds;
        int pd = (deg + 3) & ~3;
        if (pd > CAP) pd = CAP;
        for (int s = deg; s < pd; s++) d_csr[(size_t)i * CAP + s] = 0;  // safe pad -> node 0
        int cls = types[i] * 3 + pos[i];
        unsigned hb = (unsigned)__half_as_ushort(__float2half_rn(ds));
        d_p0[i] = ((unsigned)cls << 16) | hb;
    }
    int b = active ? batch[i] : -1;
    int b0 = __shfl_sync(0xffffffffu, b, 0);
    bool uni = __all_sync(0xffffffffu, b == b0);
    if (uni) {
        if ((threadIdx.x & 31) == 0) atomicAdd(&d_cnt[b0], 32.0f);
    } else if (active) {
        atomicAdd(&d_cnt[b], 1.0f);
    }
    if (i < g) out[i] = bo[0];
}

// ---------------------------------------------------------------------------
// Layer 1: gather packed (class,dis) -> 9 class sums -> reconstruct -> relu
// -> matvec Wg1 -> hs1 (fp16). QUAD per node: lane q takes every 4th group.
__device__ __forceinline__ void accum9(float* s, unsigned u) {
    int cls = (int)(u >> 16);
    float dv = __half2float(__ushort_as_half((unsigned short)(u & 0xffffu)));
#pragma unroll
    for (int k = 0; k < 9; k++) s[k] += (cls == k) ? dv : 0.0f;
}

__global__ void __launch_bounds__(256, 6)
k_agg1(const float* __restrict__ W1, const float* __restrict__ b1,
       const float* __restrict__ W2, const float* __restrict__ b2,
       const float* __restrict__ Wg0,
       const float* __restrict__ Wg1, const float* __restrict__ bg0,
       uint4* __restrict__ h_out, int n) {
    __shared__ float sA[3][HH], sB[3][HH], sW[16 * HH], sb[HH];
    int t = threadIdx.x;
    if (t < 96) {
        int which = t / 48;
        int r = (t % 48) / 16;
        int j = t % 16;
        float acc = 0.0f;
        if (which == 0) {
#pragma unroll
            for (int i = 0; i < 16; i++)
                acc = fmaf(W1[r * 16 + i] + b1[i], Wg0[i * 16 + j], acc);
            sA[r][j] = acc;
        } else {
#pragma unroll
            for (int i = 0; i < 16; i++)
                acc = fmaf(W2[r * 16 + i] + b2[i], Wg0[(16 + i) * 16 + j], acc);
            sB[r][j] = acc;
        }
    }
    sW[t] = Wg1[t];
    if (t < HH) sb[t] = bg0[t];
    __syncthreads();

    int node_raw = (blockIdx.x * blockDim.x + t) >> 2;
    bool valid = node_raw < n;
    int node = valid ? node_raw : (n - 1);
    int q = t & 3;
    int p = q & 1;
    unsigned qmask = 0xFu << ((t & 31) & ~3);

    int deg = d_deg[node];
    if (deg > CAP) deg = CAP;
    float ds = d_dis[node];

    float s[9];
#pragma unroll
    for (int k = 0; k < 9; k++) s[k] = 0.0f;

    const int4* cp4 = (const int4*)(d_csr + (size_t)node * CAP);
    int it4 = (deg + 3) >> 2;
    int it = q;
    for (; it + 4 < it4; it += 8) {      // 2 groups per lane per iter
        int4 ia = cp4[it];
        int4 ib = cp4[it + 4];
        unsigned u0 = d_p0[ia.x], u1 = d_p0[ia.y], u2 = d_p0[ia.z], u3 = d_p0[ia.w];
        unsigned u4 = d_p0[ib.x], u5 = d_p0[ib.y], u6 = d_p0[ib.z], u7 = d_p0[ib.w];
        accum9(s, u0); accum9(s, u1); accum9(s, u2); accum9(s, u3);
        accum9(s, u4); accum9(s, u5); accum9(s, u6); accum9(s, u7);
    }
    for (; it < it4; it += 4) {
        int4 ia = cp4[it];
        unsigned u0 = d_p0[ia.x], u1 = d_p0[ia.y], u2 = d_p0[ia.z], u3 = d_p0[ia.w];
        accum9(s, u0); accum9(s, u1); accum9(s, u2); accum9(s, u3);
    }

    // combine the 4 lanes' partial class sums -> all lanes hold full sums
#pragma unroll
    for (int k = 0; k < 9; k++) {
        s[k] += __shfl_xor_sync(qmask, s[k], 1, 4);
        s[k] += __shfl_xor_sync(qmask, s[k], 2, 4);
    }

    // pad correction (pad slots point at node 0), then self term
    int pads = (it4 << 2) - deg;
    if (pads > 0) {
        unsigned u0 = d_p0[0];
        int cls0 = (int)(u0 >> 16);
        float dv0 = __half2float(__ushort_as_half((unsigned short)(u0 & 0xffffu))) * (float)pads;
#pragma unroll
        for (int k = 0; k < 9; k++) s[k] -= (cls0 == k) ? dv0 : 0.0f;
    }
    {
        unsigned um = d_p0[node];
        int clsm = (int)(um >> 16);
#pragma unroll
        for (int k = 0; k < 9; k++) s[k] += (clsm == k) ? ds : 0.0f;
    }

    // reconstruct 16-dim agg: cls = ty*3 + pp
    float u0 = s[0] + s[1] + s[2], u1 = s[3] + s[4] + s[5], u2 = s[6] + s[7] + s[8];
    float v0 = s[0] + s[3] + s[6], v1 = s[1] + s[4] + s[7], v2 = s[2] + s[5] + s[8];
    float x[16];
#pragma unroll
    for (int j = 0; j < 16; j++) {
        float agg = u0 * sA[0][j] + u1 * sA[1][j] + u2 * sA[2][j]
                  + v0 * sB[0][j] + v1 * sB[1][j] + v2 * sB[2][j];
        x[j] = fmaxf(fmaf(ds, agg, sb[j]), 0.0f);
    }

    // matvec Wg1: lane computes channels p*8..p*8+7; lanes 0,1 write
    float acc[8];
#pragma unroll
    for (int k = 0; k < 8; k++) acc[k] = 0.0f;
#pragma unroll
    for (int j = 0; j < 16; j++) {
        const float* wrow = &sW[j * 16 + p * 8];
#pragma unroll
        for (int k = 0; k < 8; k++) acc[k] = fmaf(x[j], wrow[k], acc[k]);
    }

    if (valid && q < 2) {
        __half2 o[4];
#pragma unroll
        for (int k = 0; k < 4; k++)
            o[k] = __float22half2_rn(make_float2(acc[2 * k] * ds, acc[2 * k + 1] * ds));
        h_out[2 * node + p] = *(uint4*)&o[0];
    }
}

// ---------------------------------------------------------------------------
// Layer 2: gather hs1 rows (fp16 32B), relu, matvec Wg2, dot Wo -> t[n].
// QUAD per node: bit0 = channel half (16B), bit1 = group parity.
__device__ __forceinline__ void acc_half8(float* s, uint4 u) {
    const __half2* h = (const __half2*)&u;
#pragma unroll
    for (int k = 0; k < 4; k++) {
        float2 f = __half22float2(h[k]);
        s[2 * k] += f.x; s[2 * k + 1] += f.y;
    }
}

__global__ void __launch_bounds__(256, 6)
k_agg2(const uint4* __restrict__ h_in,
       const float* __restrict__ Wg2, const float* __restrict__ bg1,
       const float* __restrict__ Wo, int n) {
    __shared__ float sW[16 * HH], sb[HH], swo[HH];
    int t = threadIdx.x;
    sW[t] = Wg2[t];
    if (t < HH) { sb[t] = bg1[t]; swo[t] = Wo[t]; }
    __syncthreads();

    int node_raw = (blockIdx.x * blockDim.x + t) >> 2;
    bool valid = node_raw < n;
    int node = valid ? node_raw : (n - 1);
    int q = t & 3;
    int p = q & 1;        // channel half
    int gp = q >> 1;      // group parity
    unsigned qmask = 0xFu << ((t & 31) & ~3);
    unsigned pmask = 3u << ((t & 31) & ~1);

    int deg = d_deg[node];
    if (deg > CAP) deg = CAP;

    float s[8];
#pragma unroll
    for (int k = 0; k < 8; k++) s[k] = 0.0f;

    const int4* cp4 = (const int4*)(d_csr + (size_t)node * CAP);
    int it4 = (deg + 3) >> 2;
    int it = gp;
    for (; it + 2 < it4; it += 4) {      // 2 groups (8 edges) per pair-iter
        int4 ia = cp4[it];
        int4 ib = cp4[it + 2];
        uint4 u0 = h_in[2 * ia.x + p];
        uint4 u1 = h_in[2 * ia.y + p];
        uint4 u2 = h_in[2 * ia.z + p];
        uint4 u3 = h_in[2 * ia.w + p];
        uint4 u4 = h_in[2 * ib.x + p];
        uint4 u5 = h_in[2 * ib.y + p];
        uint4 u6 = h_in[2 * ib.z + p];
        uint4 u7 = h_in[2 * ib.w + p];
        acc_half8(s, u0); acc_half8(s, u1); acc_half8(s, u2); acc_half8(s, u3);
        acc_half8(s, u4); acc_half8(s, u5); acc_half8(s, u6); acc_half8(s, u7);
    }
    for (; it < it4; it += 2) {
        int4 ia = cp4[it];
        uint4 u0 = h_in[2 * ia.x + p];
        uint4 u1 = h_in[2 * ia.y + p];
        uint4 u2 = h_in[2 * ia.z + p];
        uint4 u3 = h_in[2 * ia.w + p];
        acc_half8(s, u0); acc_half8(s, u1); acc_half8(s, u2); acc_half8(s, u3);
    }

    // combine group-parity partials (lanes q and q^2 share channel half)
#pragma unroll
    for (int k = 0; k < 8; k++) s[k] += __shfl_xor_sync(qmask, s[k], 2, 4);

    // pad correction, then self term (post-combine: once per lane copy)
    int pads = (it4 << 2) - deg;
    if (pads > 0) {
        uint4 u = h_in[p];
        const __half2* h = (const __half2*)&u;
        float f = (float)pads;
#pragma unroll
        for (int k = 0; k < 4; k++) {
            float2 v = __half22float2(h[k]);
            s[2 * k]     -= f * v.x;
            s[2 * k + 1] -= f * v.y;
        }
    }
    acc_half8(s, h_in[2 * node + p]);

    float ds = d_dis[node];
    float x[8];
#pragma unroll
    for (int k = 0; k < 8; k++)
        x[k] = fmaxf(fmaf(ds, s[k], sb[p * 8 + k]), 0.0f);

    float acc[8];
#pragma unroll
    for (int k = 0; k < 8; k++) acc[k] = 0.0f;
#pragma unroll
    for (int r = 0; r < 2; r++) {
        float y[8];
#pragma unroll
        for (int k = 0; k < 8; k++) y[k] = __shfl_sync(pmask, x[k], r, 2);
#pragma unroll
        for (int i = 0; i < 8; i++) {
            const float* wrow = &sW[(r * 8 + i) * 16 + p * 8];
#pragma unroll
            for (int k = 0; k < 8; k++) acc[k] = fmaf(y[i], wrow[k], acc[k]);
        }
    }

    float tp = 0.0f;
#pragma unroll
    for (int k = 0; k < 8; k++) tp = fmaf(acc[k], swo[p * 8 + k], tp);
    tp *= ds;
    tp += __shfl_xor_sync(pmask, tp, 1, 2);
    if (valid && q == 0) d_t[node] = tp;
}

// ---------------------------------------------------------------------------
// Pool: gather t scalars; out[g] += (dis*(t[n]+Σt[src]) + bg2·Wo)/cnt[g].
// QUAD per node: lane q takes every 4th group.
__global__ void __launch_bounds__(256, 6)
k_pool(const int* __restrict__ batch, const float* __restrict__ bg2,
       const float* __restrict__ Wo, float* __restrict__ out, int n) {
    __shared__ float sbw;
    int t = threadIdx.x;
    if (t == 0) {
        float a = 0.0f;
#pragma unroll
        for (int k = 0; k < 16; k++) a = fmaf(bg2[k], Wo[k], a);
        sbw = a;
    }
    __syncthreads();

    int node_raw = (blockIdx.x * blockDim.x + t) >> 2;
    bool valid = node_raw < n;
    int node = valid ? node_raw : (n - 1);
    int q = t & 3;
    unsigned qmask = 0xFu << ((t & 31) & ~3);

    int deg = d_deg[node];
    if (deg > CAP) deg = CAP;

    float sum = 0.0f;
    const int4* cp4 = (const int4*)(d_csr + (size_t)node * CAP);
    int it4 = (deg + 3) >> 2;
    int it = q;
    for (; it + 4 < it4; it += 8) {
        int4 ia = cp4[it];
        int4 ib = cp4[it + 4];
        float t0 = d_t[ia.x], t1 = d_t[ia.y], t2 = d_t[ia.z], t3 = d_t[ia.w];
        float t4 = d_t[ib.x], t5 = d_t[ib.y], t6 = d_t[ib.z], t7 = d_t[ib.w];
        sum += (t0 + t1) + (t2 + t3) + (t4 + t5) + (t6 + t7);
    }
    for (; it < it4; it += 4) {
        int4 ia = cp4[it];
        sum += (d_t[ia.x] + d_t[ia.y]) + (d_t[ia.z] + d_t[ia.w]);
    }
    sum += __shfl_xor_sync(qmask, sum, 1, 4);
    sum += __shfl_xor_sync(qmask, sum, 2, 4);

    int pads = (it4 << 2) - deg;
    if (pads > 0) sum -= (float)pads * d_t[0];
    sum += d_t[node];                     // self

    float ds = d_dis[node];
    int g = batch[node];
    float c = fmaxf(d_cnt[g], 1.0f);
    float contrib = (q == 0 && valid) ? (fmaf(ds, sum, sbw)) / c : 0.0f;

    int g0 = __shfl_sync(0xffffffffu, g, 0);
    bool uni = __all_sync(0xffffffffu, g == g0);
    if (uni) {
#pragma unroll
        for (int off = 16; off > 0; off >>= 1)
            contrib += __shfl_xor_sync(0xffffffffu, contrib, off);
        if ((t & 31) == 0) atomicAdd(&out[g0], contrib);
    } else {
        if (q == 0 && valid) atomicAdd(&out[g], contrib);
    }
}

// ---------------------------------------------------------------------------
extern "C" void kernel_launch(void* const* d_in, const int* in_sizes, int n_in,
                              void* d_out, int out_size) {
    const int*   types = (const int*)d_in[0];
    const int*   pos   = (const int*)d_in[1];
    const int*   eidx  = (const int*)d_in[2];
    const int*   batch = (const int*)d_in[3];
    const float* W1  = (const float*)d_in[4];
    const float* b1  = (const float*)d_in[5];
    const float* W2  = (const float*)d_in[6];
    const float* b2  = (const float*)d_in[7];
    const float* Wg0 = (const float*)d_in[8];
    const float* bg0 = (const float*)d_in[9];
    const float* Wg1 = (const float*)d_in[10];
    const float* bg1 = (const float*)d_in[11];
    const float* Wg2 = (const float*)d_in[12];
    const float* bg2 = (const float*)d_in[13];
    const float* Wo  = (const float*)d_in[14];
    const float* bo  = (const float*)d_in[15];
    float* out = (float*)d_out;

    const int n = in_sizes[0];
    const int e = in_sizes[2] / 2;
    const int g = out_size;
    const int* src = eidx;
    const int* dst = eidx + e;

    uint4* h1;
    void *deg_p, *cnt_p;
    cudaGetSymbolAddress((void**)&h1, d_h1);
    cudaGetSymbolAddress(&deg_p, d_deg);
    cudaGetSymbolAddress(&cnt_p, d_cnt);

    const int BT = 256;
    dim3 gN((n + BT - 1) / BT);
    dim3 gQ(((n * 4) + BT - 1) / BT);   // quad-per-node kernels
    int e8 = e / 8;
    dim3 gE8((e8 + BT) / BT + 1);       // covers e8 plus scalar tail threads

    cudaMemsetAsync(deg_p, 0, (size_t)n * sizeof(int));
    cudaMemsetAsync(cnt_p, 0, (size_t)g * sizeof(float));

    k_fill<<<gE8, BT>>>(src, dst, e);
    k_node0<<<gN, BT>>>(batch, out, bo, types, pos, n, g);

    k_agg1<<<gQ, BT>>>(W1, b1, W2, b2, Wg0, Wg1, bg0, h1, n);
    k_agg2<<<gQ, BT>>>(h1, Wg2, bg1, Wo, n);
    k_pool<<<gQ, BT>>>(batch, bg2, Wo, out, n);
}

// round 13
// speedup vs baseline: 1.0811x; 1.0811x over previous
#include <cuda_runtime.h>
#include <cuda_fp16.h>
#include <stdint.h>

#define NN 100000
#define GG 1024
#define HH 16
#define CAP 128   // bucket capacity per node (mean deg 32; P(>=128) ~ 1e-30)

// Scratch (device globals; no allocation allowed)
// d_p0 packing: [0:16) fp16(dis) | [16:24) capped deg | [24:28) class
__device__ unsigned d_p0[NN];
__device__ uint4 d_h1[NN * 2];       // hs1 rows, fp16, 32B each
__device__ float d_t[NN];            // t[n] = hs2[n]·Wo
__device__ float d_dis[NN];
__device__ float d_cnt[GG];
__device__ int   d_deg[NN];          // degree counter; re-zeroed by k_node0
__device__ int   d_csr[(size_t)NN * CAP];

// ---------------------------------------------------------------------------
// Single edge pass: count + fill buckets (8 edges/thread) + zero d_cnt.
__global__ void k_fill(const int* __restrict__ src, const int* __restrict__ dst,
                       int e, int g) {
    int i = blockIdx.x * blockDim.x + threadIdx.x;
    if (i < g) d_cnt[i] = 0.0f;      // runs before k_node0 accumulates
    int e8 = e >> 3;
    if (i < e8) {
        int4 da = ((const int4*)dst)[2 * i];
        int4 db = ((const int4*)dst)[2 * i + 1];
        int4 sa = ((const int4*)src)[2 * i];
        int4 sb = ((const int4*)src)[2 * i + 1];
        int p;
        p = atomicAdd(&d_deg[da.x], 1); if (p < CAP) d_csr[(size_t)da.x * CAP + p] = sa.x;
        p = atomicAdd(&d_deg[da.y], 1); if (p < CAP) d_csr[(size_t)da.y * CAP + p] = sa.y;
        p = atomicAdd(&d_deg[da.z], 1); if (p < CAP) d_csr[(size_t)da.z * CAP + p] = sa.z;
        p = atomicAdd(&d_deg[da.w], 1); if (p < CAP) d_csr[(size_t)da.w * CAP + p] = sa.w;
        p = atomicAdd(&d_deg[db.x], 1); if (p < CAP) d_csr[(size_t)db.x * CAP + p] = sb.x;
        p = atomicAdd(&d_deg[db.y], 1); if (p < CAP) d_csr[(size_t)db.y * CAP + p] = sb.y;
        p = atomicAdd(&d_deg[db.z], 1); if (p < CAP) d_csr[(size_t)db.z * CAP + p] = sb.z;
        p = atomicAdd(&d_deg[db.w], 1); if (p < CAP) d_csr[(size_t)db.w * CAP + p] = sb.w;
    } else {
        int j = e8 * 8 + (i - e8);   // scalar tail (< 8 edges)
        if (j < e) {
            int d = dst[j];
            int p = atomicAdd(&d_deg[d], 1);
            if (p < CAP) d_csr[(size_t)d * CAP + p] = src[j];
        }
    }
}

// ---------------------------------------------------------------------------
// Node prep: dis, pad zeroing, packed (cls,deg,dis), zero d_deg for the next
// replay, batch count, out init.
__global__ void k_node0(const int* __restrict__ batch, float* __restrict__ out,
                        const float* __restrict__ bo,
                        const int* __restrict__ types, const int* __restrict__ pos,
                        int n, int g) {
    int i = blockIdx.x * blockDim.x + threadIdx.x;
    bool active = (i < n);
    if (active) {
        int degraw = d_deg[i];
        float ds = rsqrtf((float)degraw + 1.0f);
        d_dis[i] = ds;
        int deg = degraw < CAP ? degraw : CAP;
        int pd = (deg + 3) & ~3;
        for (int s = deg; s < pd; s++) d_csr[(size_t)i * CAP + s] = 0;  // safe pad -> node 0
        int cls = types[i] * 3 + pos[i];
        unsigned hb = (unsigned)__half_as_ushort(__float2half_rn(ds));
        d_p0[i] = ((unsigned)cls << 24) | ((unsigned)deg << 16) | hb;
        d_deg[i] = 0;                // replaces the memset for the next call
    }
    int b = active ? batch[i] : -1;
    int b0 = __shfl_sync(0xffffffffu, b, 0);
    bool uni = __all_sync(0xffffffffu, b == b0);
    if (uni) {
        if ((threadIdx.x & 31) == 0) atomicAdd(&d_cnt[b0], 32.0f);
    } else if (active) {
        atomicAdd(&d_cnt[b], 1.0f);
    }
    if (i < g) out[i] = bo[0];
}

// ---------------------------------------------------------------------------
// Layer 1: gather packed (cls,dis) -> 9 class sums -> reconstruct -> relu
// -> matvec Wg1 -> hs1 (fp16). Lane-PAIR per node (R11 layout).
__device__ __forceinline__ void accum9(float* s, unsigned u) {
    int cls = (int)(u >> 24);
    float dv = __half2float(__ushort_as_half((unsigned short)(u & 0xffffu)));
#pragma unroll
    for (int k = 0; k < 9; k++) s[k] += (cls == k) ? dv : 0.0f;
}

__global__ void __launch_bounds__(256, 6)
k_agg1(const float* __restrict__ W1, const float* __restrict__ b1,
       const float* __restrict__ W2, const float* __restrict__ b2,
       const float* __restrict__ Wg0,
       const float* __restrict__ Wg1, const float* __restrict__ bg0,
       uint4* __restrict__ h_out, int n) {
    __shared__ float sA[3][HH], sB[3][HH], sW[16 * HH], sb[HH];
    int t = threadIdx.x;
    if (t < 96) {
        int which = t / 48;
        int r = (t % 48) / 16;
        int j = t % 16;
        float acc = 0.0f;
        if (which == 0) {
#pragma unroll
            for (int i = 0; i < 16; i++)
                acc = fmaf(W1[r * 16 + i] + b1[i], Wg0[i * 16 + j], acc);
            sA[r][j] = acc;
        } else {
#pragma unroll
            for (int i = 0; i < 16; i++)
                acc = fmaf(W2[r * 16 + i] + b2[i], Wg0[(16 + i) * 16 + j], acc);
            sB[r][j] = acc;
        }
    }
    sW[t] = Wg1[t];
    if (t < HH) sb[t] = bg0[t];
    __syncthreads();

    int node_raw = (blockIdx.x * blockDim.x + t) >> 1;
    bool valid = node_raw < n;
    int node = valid ? node_raw : (n - 1);
    int p = t & 1;
    unsigned pmask = 3u << ((t & 31) & ~1);

    unsigned um = d_p0[node];          // self packed word (also carries deg)
    int deg = (int)((um >> 16) & 0xFFu);
    float ds = d_dis[node];

    float s[9];
#pragma unroll
    for (int k = 0; k < 9; k++) s[k] = 0.0f;

    const int4* cp4 = (const int4*)(d_csr + (size_t)node * CAP);
    int it4 = (deg + 3) >> 2;
    int it = p;
    for (; it + 2 < it4; it += 4) {      // two groups (8 edges) per iteration
        int4 ia = cp4[it];
        int4 ib = cp4[it + 2];
        unsigned u0 = d_p0[ia.x], u1 = d_p0[ia.y], u2 = d_p0[ia.z], u3 = d_p0[ia.w];
        unsigned u4 = d_p0[ib.x], u5 = d_p0[ib.y], u6 = d_p0[ib.z], u7 = d_p0[ib.w];
        accum9(s, u0); accum9(s, u1); accum9(s, u2); accum9(s, u3);
        accum9(s, u4); accum9(s, u5); accum9(s, u6); accum9(s, u7);
    }
    for (; it < it4; it += 2) {
        int4 ia = cp4[it];
        unsigned u0 = d_p0[ia.x], u1 = d_p0[ia.y], u2 = d_p0[ia.z], u3 = d_p0[ia.w];
        accum9(s, u0); accum9(s, u1); accum9(s, u2); accum9(s, u3);
    }

    // combine the two lanes' partial class sums
#pragma unroll
    for (int k = 0; k < 9; k++) s[k] += __shfl_xor_sync(pmask, s[k], 1, 2);

    // pad correction (pad slots point at node 0)
    int pads = (it4 << 2) - deg;
    if (pads > 0) {
        unsigned u0 = d_p0[0];
        int cls0 = (int)(u0 >> 24);
        float dv0 = __half2float(__ushort_as_half((unsigned short)(u0 & 0xffffu))) * (float)pads;
#pragma unroll
        for (int k = 0; k < 9; k++) s[k] -= (cls0 == k) ? dv0 : 0.0f;
    }
    // self term (fp32 dis, own class)
    {
        int clsm = (int)(um >> 24);
#pragma unroll
        for (int k = 0; k < 9; k++) s[k] += (clsm == k) ? ds : 0.0f;
    }

    // reconstruct 16-dim agg: cls = ty*3 + pp
    float u0 = s[0] + s[1] + s[2], u1 = s[3] + s[4] + s[5], u2 = s[6] + s[7] + s[8];
    float v0 = s[0] + s[3] + s[6], v1 = s[1] + s[4] + s[7], v2 = s[2] + s[5] + s[8];
    float x[16];
#pragma unroll
    for (int j = 0; j < 16; j++) {
        float agg = u0 * sA[0][j] + u1 * sA[1][j] + u2 * sA[2][j]
                  + v0 * sB[0][j] + v1 * sB[1][j] + v2 * sB[2][j];
        x[j] = fmaxf(fmaf(ds, agg, sb[j]), 0.0f);
    }

    // matvec Wg1: lane p computes output channels p*8..p*8+7
    float acc[8];
#pragma unroll
    for (int k = 0; k < 8; k++) acc[k] = 0.0f;
#pragma unroll
    for (int j = 0; j < 16; j++) {
        const float* wrow = &sW[j * 16 + p * 8];
#pragma unroll
        for (int k = 0; k < 8; k++) acc[k] = fmaf(x[j], wrow[k], acc[k]);
    }

    if (valid) {
        __half2 o[4];
#pragma unroll
        for (int k = 0; k < 4; k++)
            o[k] = __float22half2_rn(make_float2(acc[2 * k] * ds, acc[2 * k + 1] * ds));
        h_out[2 * node + p] = *(uint4*)&o[0];
    }
}

// ---------------------------------------------------------------------------
// Layer 2: gather hs1 rows (32B fp16), relu, matvec Wg2, dot Wo -> t[n].
// Lane-PAIR per node (R11 layout).
__device__ __forceinline__ void acc_half8(float* s, uint4 u) {
    const __half2* h = (const __half2*)&u;
#pragma unroll
    for (int k = 0; k < 4; k++) {
        float2 f = __half22float2(h[k]);
        s[2 * k] += f.x; s[2 * k + 1] += f.y;
    }
}

__global__ void __launch_bounds__(256, 6)
k_agg2(const uint4* __restrict__ h_in,
       const float* __restrict__ Wg2, const float* __restrict__ bg1,
       const float* __restrict__ Wo, int n) {
    __shared__ float sW[16 * HH], sb[HH], swo[HH];
    int t = threadIdx.x;
    sW[t] = Wg2[t];
    if (t < HH) { sb[t] = bg1[t]; swo[t] = Wo[t]; }
    __syncthreads();

    int node_raw = (blockIdx.x * blockDim.x + t) >> 1;
    bool valid = node_raw < n;
    int node = valid ? node_raw : (n - 1);
    int p = t & 1;
    unsigned pmask = 3u << ((t & 31) & ~1);

    int deg = (int)((d_p0[node] >> 16) & 0xFFu);

    float s[8];
    {   // self
        uint4 u = h_in[2 * node + p];
        const __half2* h = (const __half2*)&u;
#pragma unroll
        for (int k = 0; k < 4; k++) {
            float2 f = __half22float2(h[k]);
            s[2 * k] = f.x; s[2 * k + 1] = f.y;
        }
    }

    const int4* cp4 = (const int4*)(d_csr + (size_t)node * CAP);
    int it4 = (deg + 3) >> 2;
    int it = 0;
    for (; it + 2 <= it4; it += 2) {
        int4 ia = cp4[it];
        int4 ib = cp4[it + 1];
        uint4 u0 = h_in[2 * ia.x + p];
        uint4 u1 = h_in[2 * ia.y + p];
        uint4 u2 = h_in[2 * ia.z + p];
        uint4 u3 = h_in[2 * ia.w + p];
        uint4 u4 = h_in[2 * ib.x + p];
        uint4 u5 = h_in[2 * ib.y + p];
        uint4 u6 = h_in[2 * ib.z + p];
        uint4 u7 = h_in[2 * ib.w + p];
        acc_half8(s, u0); acc_half8(s, u1); acc_half8(s, u2); acc_half8(s, u3);
        acc_half8(s, u4); acc_half8(s, u5); acc_half8(s, u6); acc_half8(s, u7);
    }
    if (it < it4) {
        int4 ia = cp4[it];
        uint4 u0 = h_in[2 * ia.x + p];
        uint4 u1 = h_in[2 * ia.y + p];
        uint4 u2 = h_in[2 * ia.z + p];
        uint4 u3 = h_in[2 * ia.w + p];
        acc_half8(s, u0); acc_half8(s, u1); acc_half8(s, u2); acc_half8(s, u3);
    }
    int pads = (it4 << 2) - deg;
    if (pads > 0) {
        uint4 u = h_in[p];           // node 0 row
        const __half2* h = (const __half2*)&u;
        float f = (float)pads;
#pragma unroll
        for (int k = 0; k < 4; k++) {
            float2 v = __half22float2(h[k]);
            s[2 * k]     -= f * v.x;
            s[2 * k + 1] -= f * v.y;
        }
    }

    float ds = d_dis[node];
    float x[8];
#pragma unroll
    for (int k = 0; k < 8; k++)
        x[k] = fmaxf(fmaf(ds, s[k], sb[p * 8 + k]), 0.0f);

    float acc[8];
#pragma unroll
    for (int k = 0; k < 8; k++) acc[k] = 0.0f;
#pragma unroll
    for (int r = 0; r < 2; r++) {
        float y[8];
#pragma unroll
        for (int k = 0; k < 8; k++) y[k] = __shfl_sync(pmask, x[k], r, 2);
#pragma unroll
        for (int i = 0; i < 8; i++) {
            const float* wrow = &sW[(r * 8 + i) * 16 + p * 8];
#pragma unroll
            for (int k = 0; k < 8; k++) acc[k] = fmaf(y[i], wrow[k], acc[k]);
        }
    }

    float tp = 0.0f;
#pragma unroll
    for (int k = 0; k < 8; k++) tp = fmaf(acc[k], swo[p * 8 + k], tp);
    tp *= ds;
    tp += __shfl_xor_sync(pmask, tp, 1, 2);
    if (valid && p == 0) d_t[node] = tp;
}

// ---------------------------------------------------------------------------
// Pool: gather t scalars; out[g] += (dis*(t[n]+Σt[src]) + bg2·Wo)/cnt[g].
// Lane-PAIR per node (R11 layout).
__global__ void __launch_bounds__(256, 6)
k_pool(const int* __restrict__ batch, const float* __restrict__ bg2,
       const float* __restrict__ Wo, float* __restrict__ out, int n) {
    __shared__ float sbw;
    int t = threadIdx.x;
    if (t == 0) {
        float a = 0.0f;
#pragma unroll
        for (int k = 0; k < 16; k++) a = fmaf(bg2[k], Wo[k], a);
        sbw = a;
    }
    __syncthreads();

    int node_raw = (blockIdx.x * blockDim.x + t) >> 1;
    bool valid = node_raw < n;
    int node = valid ? node_raw : (n - 1);
    int p = t & 1;
    unsigned pmask = 3u << ((t & 31) & ~1);

    int deg = (int)((d_p0[node] >> 16) & 0xFFu);

    float sum = 0.0f;
    const int4* cp4 = (const int4*)(d_csr + (size_t)node * CAP);
    int it4 = (deg + 3) >> 2;
    int it = p;
    for (; it + 2 < it4; it += 4) {
        int4 ia = cp4[it];
        int4 ib = cp4[it + 2];
        float t0 = d_t[ia.x], t1 = d_t[ia.y], t2 = d_t[ia.z], t3 = d_t[ia.w];
        float t4 = d_t[ib.x], t5 = d_t[ib.y], t6 = d_t[ib.z], t7 = d_t[ib.w];
        sum += (t0 + t1) + (t2 + t3) + (t4 + t5) + (t6 + t7);
    }
    for (; it < it4; it += 2) {
        int4 ia = cp4[it];
        sum += (d_t[ia.x] + d_t[ia.y]) + (d_t[ia.z] + d_t[ia.w]);
    }
    sum += __shfl_xor_sync(pmask, sum, 1, 2);

    int pads = (it4 << 2) - deg;
    if (pads > 0) sum -= (float)pads * d_t[0];
    sum += d_t[node];                     // self

    float ds = d_dis[node];
    int g = batch[node];
    float c = fmaxf(d_cnt[g], 1.0f);
    float contrib = (p == 0 && valid) ? (fmaf(ds, sum, sbw)) / c : 0.0f;

    int g0 = __shfl_sync(0xffffffffu, g, 0);
    bool uni = __all_sync(0xffffffffu, g == g0);
    if (uni) {
#pragma unroll
        for (int off = 16; off > 0; off >>= 1)
            contrib += __shfl_xor_sync(0xffffffffu, contrib, off);
        if ((t & 31) == 0) atomicAdd(&out[g0], contrib);
    } else {
        if (p == 0 && valid) atomicAdd(&out[g], contrib);
    }
}

// ---------------------------------------------------------------------------
extern "C" void kernel_launch(void* const* d_in, const int* in_sizes, int n_in,
                              void* d_out, int out_size) {
    const int*   types = (const int*)d_in[0];
    const int*   pos   = (const int*)d_in[1];
    const int*   eidx  = (const int*)d_in[2];
    const int*   batch = (const int*)d_in[3];
    const float* W1  = (const float*)d_in[4];
    const float* b1  = (const float*)d_in[5];
    const float* W2  = (const float*)d_in[6];
    const float* b2  = (const float*)d_in[7];
    const float* Wg0 = (const float*)d_in[8];
    const float* bg0 = (const float*)d_in[9];
    const float* Wg1 = (const float*)d_in[10];
    const float* bg1 = (const float*)d_in[11];
    const float* Wg2 = (const float*)d_in[12];
    const float* bg2 = (const float*)d_in[13];
    const float* Wo  = (const float*)d_in[14];
    const float* bo  = (const float*)d_in[15];
    float* out = (float*)d_out;

    const int n = in_sizes[0];
    const int e = in_sizes[2] / 2;
    const int g = out_size;
    const int* src = eidx;
    const int* dst = eidx + e;

    uint4* h1;
    cudaGetSymbolAddress((void**)&h1, d_h1);

    const int BT = 256;
    dim3 gN((n + BT - 1) / BT);
    dim3 gP(((n * 2) + BT - 1) / BT);   // pair-per-node kernels
    int e8 = e / 8;
    dim3 gE8((e8 + BT) / BT + 1);       // covers e8 plus scalar tail threads

    k_fill<<<gE8, BT>>>(src, dst, e, g);                 // count+fill+zero cnt
    k_node0<<<gN, BT>>>(batch, out, bo, types, pos, n, g);

    k_agg1<<<gP, BT>>>(W1, b1, W2, b2, Wg0, Wg1, bg0, h1, n);
    k_agg2<<<gP, BT>>>(h1, Wg2, bg1, Wo, n);
    k_pool<<<gP, BT>>>(batch, bg2, Wo, out, n);
}

// round 14
// speedup vs baseline: 1.1274x; 1.0429x over previous
#include <cuda_runtime.h>
#include <cuda_fp16.h>
#include <stdint.h>

#define NN 100000
#define GG 1024
#define HH 16
#define CAP 128   // bucket capacity per node (mean deg 32; P(>=128) ~ 1e-30)

// Scratch (device globals; no allocation allowed)
// d_p0 packing: [0:16) fp16(dis) | [16:24) capped deg | [24:28) class
__device__ unsigned d_p0[NN];
__device__ uint4 d_h1[NN * 2];       // hs1 rows, fp16, 32B each
__device__ float d_t[NN];            // t[n] = hs2[n]·Wo
__device__ float d_dis[NN];
__device__ float d_cnt[GG];
__device__ int   d_deg[NN];          // degree counter; re-zeroed by k_node0
__device__ int   d_csr[(size_t)NN * CAP];

// ---------------------------------------------------------------------------
// Single edge pass: count + fill buckets (8 edges/thread) + zero d_cnt.
// PDL: edge-list loads prefetched BEFORE the grid-dependency sync (inputs are
// graph-constant); all global writes after the sync.
__global__ void k_fill(const int* __restrict__ src, const int* __restrict__ dst,
                       int e, int g) {
    int i = blockIdx.x * blockDim.x + threadIdx.x;
    int e8 = e >> 3;
    bool full = (i < e8);
    int4 da, db, sa, sb;
    if (full) {                       // prefetch (overlaps predecessor tail)
        da = ((const int4*)dst)[2 * i];
        db = ((const int4*)dst)[2 * i + 1];
        sa = ((const int4*)src)[2 * i];
        sb = ((const int4*)src)[2 * i + 1];
    }
    cudaGridDependencySynchronize();
    if (i < g) d_cnt[i] = 0.0f;
    if (full) {
        int p;
        p = atomicAdd(&d_deg[da.x], 1); if (p < CAP) d_csr[(size_t)da.x * CAP + p] = sa.x;
        p = atomicAdd(&d_deg[da.y], 1); if (p < CAP) d_csr[(size_t)da.y * CAP + p] = sa.y;
        p = atomicAdd(&d_deg[da.z], 1); if (p < CAP) d_csr[(size_t)da.z * CAP + p] = sa.z;
        p = atomicAdd(&d_deg[da.w], 1); if (p < CAP) d_csr[(size_t)da.w * CAP + p] = sa.w;
        p = atomicAdd(&d_deg[db.x], 1); if (p < CAP) d_csr[(size_t)db.x * CAP + p] = sb.x;
        p = atomicAdd(&d_deg[db.y], 1); if (p < CAP) d_csr[(size_t)db.y * CAP + p] = sb.y;
        p = atomicAdd(&d_deg[db.z], 1); if (p < CAP) d_csr[(size_t)db.z * CAP + p] = sb.z;
        p = atomicAdd(&d_deg[db.w], 1); if (p < CAP) d_csr[(size_t)db.w * CAP + p] = sb.w;
    } else {
        int j = e8 * 8 + (i - e8);   // scalar tail (< 8 edges)
        if (j < e) {
            int d = dst[j];
            int p = atomicAdd(&d_deg[d], 1);
            if (p < CAP) d_csr[(size_t)d * CAP + p] = src[j];
        }
    }
}

// ---------------------------------------------------------------------------
// Node prep: dis, pad zeroing, packed (cls,deg,dis), zero d_deg for the next
// replay, batch count, out init. out-init is fill-independent -> pre-sync.
__global__ void k_node0(const int* __restrict__ batch, float* __restrict__ out,
                        const float* __restrict__ bo,
                        const int* __restrict__ types, const int* __restrict__ pos,
                        int n, int g) {
    int i = blockIdx.x * blockDim.x + threadIdx.x;
    bool active = (i < n);
    if (i < g) out[i] = bo[0];       // pre-sync: out not touched by k_fill
    int cls = 0;
    if (active) cls = types[i] * 3 + pos[i];
    cudaGridDependencySynchronize();
    if (active) {
        int degraw = d_deg[i];
        float ds = rsqrtf((float)degraw + 1.0f);
        d_dis[i] = ds;
        int deg = degraw < CAP ? degraw : CAP;
        int pd = (deg + 3) & ~3;
        for (int s = deg; s < pd; s++) d_csr[(size_t)i * CAP + s] = 0;  // safe pad -> node 0
        unsigned hb = (unsigned)__half_as_ushort(__float2half_rn(ds));
        d_p0[i] = ((unsigned)cls << 24) | ((unsigned)deg << 16) | hb;
        d_deg[i] = 0;                // replaces the memset for the next call
    }
    int b = active ? batch[i] : -1;
    int b0 = __shfl_sync(0xffffffffu, b, 0);
    bool uni = __all_sync(0xffffffffu, b == b0);
    if (uni) {
        if ((threadIdx.x & 31) == 0) atomicAdd(&d_cnt[b0], 32.0f);
    } else if (active) {
        atomicAdd(&d_cnt[b], 1.0f);
    }
}

// ---------------------------------------------------------------------------
// Layer 1: gather packed (cls,dis) -> 9 class sums -> reconstruct -> relu
// -> matvec Wg1 -> hs1 (fp16). Lane-PAIR per node.
__device__ __forceinline__ void accum9(float* s, unsigned u) {
    int cls = (int)(u >> 24);
    float dv = __half2float(__ushort_as_half((unsigned short)(u & 0xffffu)));
#pragma unroll
    for (int k = 0; k < 9; k++) s[k] += (cls == k) ? dv : 0.0f;
}

__global__ void __launch_bounds__(256, 6)
k_agg1(const float* __restrict__ W1, const float* __restrict__ b1,
       const float* __restrict__ W2, const float* __restrict__ b2,
       const float* __restrict__ Wg0,
       const float* __restrict__ Wg1, const float* __restrict__ bg0,
       uint4* __restrict__ h_out, int n) {
    __shared__ float sA[3][HH], sB[3][HH], sW[16 * HH], sb[HH];
    int t = threadIdx.x;
    // prologue: weights only (graph-constant inputs) -> pre-sync
    if (t < 96) {
        int which = t / 48;
        int r = (t % 48) / 16;
        int j = t % 16;
        float acc = 0.0f;
        if (which == 0) {
#pragma unroll
            for (int i = 0; i < 16; i++)
                acc = fmaf(W1[r * 16 + i] + b1[i], Wg0[i * 16 + j], acc);
            sA[r][j] = acc;
        } else {
#pragma unroll
            for (int i = 0; i < 16; i++)
                acc = fmaf(W2[r * 16 + i] + b2[i], Wg0[(16 + i) * 16 + j], acc);
            sB[r][j] = acc;
        }
    }
    sW[t] = Wg1[t];
    if (t < HH) sb[t] = bg0[t];
    cudaGridDependencySynchronize();
    __syncthreads();

    int node_raw = (blockIdx.x * blockDim.x + t) >> 1;
    bool valid = node_raw < n;
    int node = valid ? node_raw : (n - 1);
    int p = t & 1;
    unsigned pmask = 3u << ((t & 31) & ~1);

    unsigned um = d_p0[node];          // self packed word (also carries deg)
    int deg = (int)((um >> 16) & 0xFFu);
    float ds = d_dis[node];

    float s[9];
#pragma unroll
    for (int k = 0; k < 9; k++) s[k] = 0.0f;

    const int4* cp4 = (const int4*)(d_csr + (size_t)node * CAP);
    int it4 = (deg + 3) >> 2;
    int it = p;
    for (; it + 2 < it4; it += 4) {      // two groups (8 edges) per iteration
        int4 ia = cp4[it];
        int4 ib = cp4[it + 2];
        unsigned u0 = d_p0[ia.x], u1 = d_p0[ia.y], u2 = d_p0[ia.z], u3 = d_p0[ia.w];
        unsigned u4 = d_p0[ib.x], u5 = d_p0[ib.y], u6 = d_p0[ib.z], u7 = d_p0[ib.w];
        accum9(s, u0); accum9(s, u1); accum9(s, u2); accum9(s, u3);
        accum9(s, u4); accum9(s, u5); accum9(s, u6); accum9(s, u7);
    }
    for (; it < it4; it += 2) {
        int4 ia = cp4[it];
        unsigned u0 = d_p0[ia.x], u1 = d_p0[ia.y], u2 = d_p0[ia.z], u3 = d_p0[ia.w];
        accum9(s, u0); accum9(s, u1); accum9(s, u2); accum9(s, u3);
    }

    // combine the two lanes' partial class sums
#pragma unroll
    for (int k = 0; k < 9; k++) s[k] += __shfl_xor_sync(pmask, s[k], 1, 2);

    // pad correction (pad slots point at node 0)
    int pads = (it4 << 2) - deg;
    if (pads > 0) {
        unsigned u0 = d_p0[0];
        int cls0 = (int)(u0 >> 24);
        float dv0 = __half2float(__ushort_as_half((unsigned short)(u0 & 0xffffu))) * (float)pads;
#pragma unroll
        for (int k = 0; k < 9; k++) s[k] -= (cls0 == k) ? dv0 : 0.0f;
    }
    // self term (fp32 dis, own class)
    {
        int clsm = (int)(um >> 24);
#pragma unroll
        for (int k = 0; k < 9; k++) s[k] += (clsm == k) ? ds : 0.0f;
    }

    // reconstruct 16-dim agg: cls = ty*3 + pp
    float u0 = s[0] + s[1] + s[2], u1 = s[3] + s[4] + s[5], u2 = s[6] + s[7] + s[8];
    float v0 = s[0] + s[3] + s[6], v1 = s[1] + s[4] + s[7], v2 = s[2] + s[5] + s[8];
    float x[16];
#pragma unroll
    for (int j = 0; j < 16; j++) {
        float agg = u0 * sA[0][j] + u1 * sA[1][j] + u2 * sA[2][j]
                  + v0 * sB[0][j] + v1 * sB[1][j] + v2 * sB[2][j];
        x[j] = fmaxf(fmaf(ds, agg, sb[j]), 0.0f);
    }

    // matvec Wg1: lane p computes output channels p*8..p*8+7
    float acc[8];
#pragma unroll
    for (int k = 0; k < 8; k++) acc[k] = 0.0f;
#pragma unroll
    for (int j = 0; j < 16; j++) {
        const float* wrow = &sW[j * 16 + p * 8];
#pragma unroll
        for (int k = 0; k < 8; k++) acc[k] = fmaf(x[j], wrow[k], acc[k]);
    }

    if (valid) {
        __half2 o[4];
#pragma unroll
        for (int k = 0; k < 4; k++)
            o[k] = __float22half2_rn(make_float2(acc[2 * k] * ds, acc[2 * k + 1] * ds));
        h_out[2 * node + p] = *(uint4*)&o[0];
    }
}

// ---------------------------------------------------------------------------
// Layer 2: gather hs1 rows (32B fp16), relu, rank-1 epilogue:
//   t[n] = ds * x · wt,   wt = Wg2 @ Wo   (no relu after last matvec!)
__device__ __forceinline__ void acc_half8(float* s, uint4 u) {
    const __half2* h = (const __half2*)&u;
#pragma unroll
    for (int k = 0; k < 4; k++) {
        float2 f = __half22float2(h[k]);
        s[2 * k] += f.x; s[2 * k + 1] += f.y;
    }
}

__global__ void __launch_bounds__(256, 6)
k_agg2(const uint4* __restrict__ h_in,
       const float* __restrict__ Wg2, const float* __restrict__ bg1,
       const float* __restrict__ Wo, int n) {
    __shared__ float swt[HH], sb[HH];
    int t = threadIdx.x;
    if (t < HH) {
        float a = 0.0f;
#pragma unroll
        for (int m = 0; m < 16; m++) a = fmaf(Wg2[t * 16 + m], Wo[m], a);
        swt[t] = a;
        sb[t] = bg1[t];
    }
    cudaGridDependencySynchronize();
    __syncthreads();

    int node_raw = (blockIdx.x * blockDim.x + t) >> 1;
    bool valid = node_raw < n;
    int node = valid ? node_raw : (n - 1);
    int p = t & 1;
    unsigned pmask = 3u << ((t & 31) & ~1);

    int deg = (int)((d_p0[node] >> 16) & 0xFFu);

    float s[8];
    {   // self
        uint4 u = h_in[2 * node + p];
        const __half2* h = (const __half2*)&u;
#pragma unroll
        for (int k = 0; k < 4; k++) {
            float2 f = __half22float2(h[k]);
            s[2 * k] = f.x; s[2 * k + 1] = f.y;
        }
    }

    const int4* cp4 = (const int4*)(d_csr + (size_t)node * CAP);
    int it4 = (deg + 3) >> 2;
    int it = 0;
    for (; it + 2 <= it4; it += 2) {
        int4 ia = cp4[it];
        int4 ib = cp4[it + 1];
        uint4 u0 = h_in[2 * ia.x + p];
        uint4 u1 = h_in[2 * ia.y + p];
        uint4 u2 = h_in[2 * ia.z + p];
        uint4 u3 = h_in[2 * ia.w + p];
        uint4 u4 = h_in[2 * ib.x + p];
        uint4 u5 = h_in[2 * ib.y + p];
        uint4 u6 = h_in[2 * ib.z + p];
        uint4 u7 = h_in[2 * ib.w + p];
        acc_half8(s, u0); acc_half8(s, u1); acc_half8(s, u2); acc_half8(s, u3);
        acc_half8(s, u4); acc_half8(s, u5); acc_half8(s, u6); acc_half8(s, u7);
    }
    if (it < it4) {
        int4 ia = cp4[it];
        uint4 u0 = h_in[2 * ia.x + p];
        uint4 u1 = h_in[2 * ia.y + p];
        uint4 u2 = h_in[2 * ia.z + p];
        uint4 u3 = h_in[2 * ia.w + p];
        acc_half8(s, u0); acc_half8(s, u1); acc_half8(s, u2); acc_half8(s, u3);
    }
    int pads = (it4 << 2) - deg;
    if (pads > 0) {
        uint4 u = h_in[p];           // node 0 row
        const __half2* h = (const __half2*)&u;
        float f = (float)pads;
#pragma unroll
        for (int k = 0; k < 4; k++) {
            float2 v = __half22float2(h[k]);
            s[2 * k]     -= f * v.x;
            s[2 * k + 1] -= f * v.y;
        }
    }

    float ds = d_dis[node];
    float tp = 0.0f;
#pragma unroll
    for (int k = 0; k < 8; k++) {
        float xk = fmaxf(fmaf(ds, s[k], sb[p * 8 + k]), 0.0f);
        tp = fmaf(xk, swt[p * 8 + k], tp);
    }
    tp *= ds;
    tp += __shfl_xor_sync(pmask, tp, 1, 2);
    if (valid && p == 0) d_t[node] = tp;
}

// ---------------------------------------------------------------------------
// Pool: gather t scalars; out[g] += (dis*(t[n]+Σt[src]) + bg2·Wo)/cnt[g].
__global__ void __launch_bounds__(256, 6)
k_pool(const int* __restrict__ batch, const float* __restrict__ bg2,
       const float* __restrict__ Wo, float* __restrict__ out, int n) {
    __shared__ float sbw;
    int t = threadIdx.x;
    if (t == 0) {
        float a = 0.0f;
#pragma unroll
        for (int k = 0; k < 16; k++) a = fmaf(bg2[k], Wo[k], a);
        sbw = a;
    }
    cudaGridDependencySynchronize();
    __syncthreads();

    int node_raw = (blockIdx.x * blockDim.x + t) >> 1;
    bool valid = node_raw < n;
    int node = valid ? node_raw : (n - 1);
    int p = t & 1;
    unsigned pmask = 3u << ((t & 31) & ~1);

    int deg = (int)((d_p0[node] >> 16) & 0xFFu);

    float sum = 0.0f;
    const int4* cp4 = (const int4*)(d_csr + (size_t)node * CAP);
    int it4 = (deg + 3) >> 2;
    int it = p;
    for (; it + 2 < it4; it += 4) {
        int4 ia = cp4[it];
        int4 ib = cp4[it + 2];
        float t0 = d_t[ia.x], t1 = d_t[ia.y], t2 = d_t[ia.z], t3 = d_t[ia.w];
        float t4 = d_t[ib.x], t5 = d_t[ib.y], t6 = d_t[ib.z], t7 = d_t[ib.w];
        sum += (t0 + t1) + (t2 + t3) + (t4 + t5) + (t6 + t7);
    }
    for (; it < it4; it += 2) {
        int4 ia = cp4[it];
        sum += (d_t[ia.x] + d_t[ia.y]) + (d_t[ia.z] + d_t[ia.w]);
    }
    sum += __shfl_xor_sync(pmask, sum, 1, 2);

    int pads = (it4 << 2) - deg;
    if (pads > 0) sum -= (float)pads * d_t[0];
    sum += d_t[node];                     // self

    float ds = d_dis[node];
    int g = batch[node];
    float c = fmaxf(d_cnt[g], 1.0f);
    float contrib = (p == 0 && valid) ? (fmaf(ds, sum, sbw)) / c : 0.0f;

    int g0 = __shfl_sync(0xffffffffu, g, 0);
    bool uni = __all_sync(0xffffffffu, g == g0);
    if (uni) {
#pragma unroll
        for (int off = 16; off > 0; off >>= 1)
            contrib += __shfl_xor_sync(0xffffffffu, contrib, off);
        if ((t & 31) == 0) atomicAdd(&out[g0], contrib);
    } else {
        if (p == 0 && valid) atomicAdd(&out[g], contrib);
    }
}

// ---------------------------------------------------------------------------
template <typename K, typename... Args>
static inline void launch_pdl(K kernel, dim3 grid, dim3 block, Args... args) {
    cudaLaunchConfig_t cfg = {};
    cfg.gridDim = grid;
    cfg.blockDim = block;
    cfg.dynamicSmemBytes = 0;
    cfg.stream = 0;
    cudaLaunchAttribute attr[1];
    attr[0].id = cudaLaunchAttributeProgrammaticStreamSerialization;
    attr[0].val.programmaticStreamSerializationAllowed = 1;
    cfg.attrs = attr;
    cfg.numAttrs = 1;
    cudaLaunchKernelEx(&cfg, kernel, args...);
}

extern "C" void kernel_launch(void* const* d_in, const int* in_sizes, int n_in,
                              void* d_out, int out_size) {
    const int*   types = (const int*)d_in[0];
    const int*   pos   = (const int*)d_in[1];
    const int*   eidx  = (const int*)d_in[2];
    const int*   batch = (const int*)d_in[3];
    const float* W1  = (const float*)d_in[4];
    const float* b1  = (const float*)d_in[5];
    const float* W2  = (const float*)d_in[6];
    const float* b2  = (const float*)d_in[7];
    const float* Wg0 = (const float*)d_in[8];
    const float* bg0 = (const float*)d_in[9];
    const float* Wg1 = (const float*)d_in[10];
    const float* bg1 = (const float*)d_in[11];
    const float* Wg2 = (const float*)d_in[12];
    const float* bg2 = (const float*)d_in[13];
    const float* Wo  = (const float*)d_in[14];
    const float* bo  = (const float*)d_in[15];
    float* out = (float*)d_out;

    const int n = in_sizes[0];
    const int e = in_sizes[2] / 2;
    const int g = out_size;
    const int* src = eidx;
    const int* dst = eidx + e;

    uint4* h1;
    cudaGetSymbolAddress((void**)&h1, d_h1);

    const int BT = 256;
    dim3 gN((n + BT - 1) / BT);
    dim3 gP(((n * 2) + BT - 1) / BT);   // pair-per-node kernels
    int e8 = e / 8;
    dim3 gE8((e8 + BT) / BT + 1);       // covers e8 plus scalar tail threads
    dim3 bT(BT);

    launch_pdl(k_fill,  gE8, bT, src, dst, e, g);
    launch_pdl(k_node0, gN,  bT, batch, out, bo, types, pos, n, g);
    launch_pdl(k_agg1,  gP,  bT, W1, b1, W2, b2, Wg0, Wg1, bg0, h1, n);
    launch_pdl(k_agg2,  gP,  bT, (const uint4*)h1, Wg2, bg1, Wo, n);
    launch_pdl(k_pool,  gP,  bT, batch, bg2, Wo, out, n);
}

// round 15
// speedup vs baseline: 1.1289x; 1.0013x over previous
#include <cuda_runtime.h>
#include <cuda_fp16.h>
#include <stdint.h>

#define NN 100000
#define GG 1024
#define HH 16
#define CAP 128   // bucket capacity per node (mean deg 32; P(>=128) ~ 1e-30)

// Scratch (device globals; no allocation allowed)
// d_p0 packing (uint16): [0:8) capped deg | [8:12) class  -> 200KB, L1-resident
__device__ unsigned short d_p0[NN];
__device__ uint4 d_h1[NN * 2];       // hs1 rows, fp16, 32B each
__device__ __half d_t[NN];           // t[n] = hs2[n]·Wo  (fp16, 200KB table)
__device__ float d_dis[NN];
__device__ float d_cnt[GG];
__device__ int   d_deg[NN];          // degree counter; re-zeroed by k_node0
__device__ int   d_csr[(size_t)NN * CAP];

// ---------------------------------------------------------------------------
// Single edge pass: count + fill buckets (8 edges/thread) + zero d_cnt.
__global__ void k_fill(const int* __restrict__ src, const int* __restrict__ dst,
                       int e, int g) {
    int i = blockIdx.x * blockDim.x + threadIdx.x;
    int e8 = e >> 3;
    bool full = (i < e8);
    int4 da, db, sa, sb;
    if (full) {                       // prefetch (overlaps predecessor tail)
        da = ((const int4*)dst)[2 * i];
        db = ((const int4*)dst)[2 * i + 1];
        sa = ((const int4*)src)[2 * i];
        sb = ((const int4*)src)[2 * i + 1];
    }
    cudaGridDependencySynchronize();
    if (i < g) d_cnt[i] = 0.0f;
    if (full) {
        int p;
        p = atomicAdd(&d_deg[da.x], 1); if (p < CAP) d_csr[(size_t)da.x * CAP + p] = sa.x;
        p = atomicAdd(&d_deg[da.y], 1); if (p < CAP) d_csr[(size_t)da.y * CAP + p] = sa.y;
        p = atomicAdd(&d_deg[da.z], 1); if (p < CAP) d_csr[(size_t)da.z * CAP + p] = sa.z;
        p = atomicAdd(&d_deg[da.w], 1); if (p < CAP) d_csr[(size_t)da.w * CAP + p] = sa.w;
        p = atomicAdd(&d_deg[db.x], 1); if (p < CAP) d_csr[(size_t)db.x * CAP + p] = sb.x;
        p = atomicAdd(&d_deg[db.y], 1); if (p < CAP) d_csr[(size_t)db.y * CAP + p] = sb.y;
        p = atomicAdd(&d_deg[db.z], 1); if (p < CAP) d_csr[(size_t)db.z * CAP + p] = sb.z;
        p = atomicAdd(&d_deg[db.w], 1); if (p < CAP) d_csr[(size_t)db.w * CAP + p] = sb.w;
    } else {
        int j = e8 * 8 + (i - e8);   // scalar tail (< 8 edges)
        if (j < e) {
            int d = dst[j];
            int p = atomicAdd(&d_deg[d], 1);
            if (p < CAP) d_csr[(size_t)d * CAP + p] = src[j];
        }
    }
}

// ---------------------------------------------------------------------------
// Node prep: dis, pad zeroing, packed (cls,deg) uint16, zero d_deg, batch
// count, out init.
__global__ void k_node0(const int* __restrict__ batch, float* __restrict__ out,
                        const float* __restrict__ bo,
                        const int* __restrict__ types, const int* __restrict__ pos,
                        int n, int g) {
    int i = blockIdx.x * blockDim.x + threadIdx.x;
    bool active = (i < n);
    if (i < g) out[i] = bo[0];       // pre-sync: out not touched by k_fill
    int cls = 0;
    if (active) cls = types[i] * 3 + pos[i];
    cudaGridDependencySynchronize();
    if (active) {
        int degraw = d_deg[i];
        float ds = rsqrtf((float)degraw + 1.0f);
        d_dis[i] = ds;
        int deg = degraw < CAP ? degraw : CAP;
        int pd = (deg + 3) & ~3;
        for (int s = deg; s < pd; s++) d_csr[(size_t)i * CAP + s] = 0;  // safe pad -> node 0
        d_p0[i] = (unsigned short)((cls << 8) | deg);
        d_deg[i] = 0;                // replaces the memset for the next call
    }
    int b = active ? batch[i] : -1;
    int b0 = __shfl_sync(0xffffffffu, b, 0);
    bool uni = __all_sync(0xffffffffu, b == b0);
    if (uni) {
        if ((threadIdx.x & 31) == 0) atomicAdd(&d_cnt[b0], 32.0f);
    } else if (active) {
        atomicAdd(&d_cnt[b], 1.0f);
    }
}

// ---------------------------------------------------------------------------
// Layer 1: gather packed (cls,deg) uint16 -> 9 class sums (dis via smem LUT)
// -> reconstruct -> relu -> matvec Wg1 -> hs1 (fp16). Lane-PAIR per node.
__device__ __forceinline__ void accum9u(float* s, unsigned v, const float* sDis) {
    int cls = (int)(v >> 8);
    float dv = sDis[v & 0xFFu];
#pragma unroll
    for (int k = 0; k < 9; k++) s[k] += (cls == k) ? dv : 0.0f;
}

__global__ void __launch_bounds__(256, 6)
k_agg1(const float* __restrict__ W1, const float* __restrict__ b1,
       const float* __restrict__ W2, const float* __restrict__ b2,
       const float* __restrict__ Wg0,
       const float* __restrict__ Wg1, const float* __restrict__ bg0,
       uint4* __restrict__ h_out, int n) {
    __shared__ float sA[3][HH], sB[3][HH], sW[16 * HH], sb[HH];
    __shared__ float sDis[CAP + 1];
    int t = threadIdx.x;
    // prologue: weights + dis LUT (input/constant only) -> pre-sync
    if (t < 96) {
        int which = t / 48;
        int r = (t % 48) / 16;
        int j = t % 16;
        float acc = 0.0f;
        if (which == 0) {
#pragma unroll
            for (int i = 0; i < 16; i++)
                acc = fmaf(W1[r * 16 + i] + b1[i], Wg0[i * 16 + j], acc);
            sA[r][j] = acc;
        } else {
#pragma unroll
            for (int i = 0; i < 16; i++)
                acc = fmaf(W2[r * 16 + i] + b2[i], Wg0[(16 + i) * 16 + j], acc);
            sB[r][j] = acc;
        }
    }
    sW[t] = Wg1[t];
    if (t < HH) sb[t] = bg0[t];
    if (t <= CAP) sDis[t] = rsqrtf((float)t + 1.0f);
    cudaGridDependencySynchronize();
    __syncthreads();

    int node_raw = (blockIdx.x * blockDim.x + t) >> 1;
    bool valid = node_raw < n;
    int node = valid ? node_raw : (n - 1);
    int p = t & 1;
    unsigned pmask = 3u << ((t & 31) & ~1);

    unsigned um = d_p0[node];          // self packed word (also carries deg)
    int deg = (int)(um & 0xFFu);
    float ds = d_dis[node];

    float s[9];
#pragma unroll
    for (int k = 0; k < 9; k++) s[k] = 0.0f;

    const int4* cp4 = (const int4*)(d_csr + (size_t)node * CAP);
    int it4 = (deg + 3) >> 2;
    int it = p;
    for (; it + 2 < it4; it += 4) {      // two groups (8 edges) per iteration
        int4 ia = cp4[it];
        int4 ib = cp4[it + 2];
        unsigned u0 = d_p0[ia.x], u1 = d_p0[ia.y], u2 = d_p0[ia.z], u3 = d_p0[ia.w];
        unsigned u4 = d_p0[ib.x], u5 = d_p0[ib.y], u6 = d_p0[ib.z], u7 = d_p0[ib.w];
        accum9u(s, u0, sDis); accum9u(s, u1, sDis); accum9u(s, u2, sDis); accum9u(s, u3, sDis);
        accum9u(s, u4, sDis); accum9u(s, u5, sDis); accum9u(s, u6, sDis); accum9u(s, u7, sDis);
    }
    for (; it < it4; it += 2) {
        int4 ia = cp4[it];
        unsigned u0 = d_p0[ia.x], u1 = d_p0[ia.y], u2 = d_p0[ia.z], u3 = d_p0[ia.w];
        accum9u(s, u0, sDis); accum9u(s, u1, sDis); accum9u(s, u2, sDis); accum9u(s, u3, sDis);
    }

    // combine the two lanes' partial class sums
#pragma unroll
    for (int k = 0; k < 9; k++) s[k] += __shfl_xor_sync(pmask, s[k], 1, 2);

    // pad correction (pad slots point at node 0)
    int pads = (it4 << 2) - deg;
    if (pads > 0) {
        unsigned u0 = d_p0[0];
        int cls0 = (int)(u0 >> 8);
        float dv0 = sDis[u0 & 0xFFu] * (float)pads;
#pragma unroll
        for (int k = 0; k < 9; k++) s[k] -= (cls0 == k) ? dv0 : 0.0f;
    }
    // self term (fp32 dis, own class)
    {
        int clsm = (int)(um >> 8);
#pragma unroll
        for (int k = 0; k < 9; k++) s[k] += (clsm == k) ? ds : 0.0f;
    }

    // reconstruct 16-dim agg: cls = ty*3 + pp
    float u0 = s[0] + s[1] + s[2], u1 = s[3] + s[4] + s[5], u2 = s[6] + s[7] + s[8];
    float v0 = s[0] + s[3] + s[6], v1 = s[1] + s[4] + s[7], v2 = s[2] + s[5] + s[8];
    float x[16];
#pragma unroll
    for (int j = 0; j < 16; j++) {
        float agg = u0 * sA[0][j] + u1 * sA[1][j] + u2 * sA[2][j]
                  + v0 * sB[0][j] + v1 * sB[1][j] + v2 * sB[2][j];
        x[j] = fmaxf(fmaf(ds, agg, sb[j]), 0.0f);
    }

    // matvec Wg1: lane p computes output channels p*8..p*8+7
    float acc[8];
#pragma unroll
    for (int k = 0; k < 8; k++) acc[k] = 0.0f;
#pragma unroll
    for (int j = 0; j < 16; j++) {
        const float* wrow = &sW[j * 16 + p * 8];
#pragma unroll
        for (int k = 0; k < 8; k++) acc[k] = fmaf(x[j], wrow[k], acc[k]);
    }

    if (valid) {
        __half2 o[4];
#pragma unroll
        for (int k = 0; k < 4; k++)
            o[k] = __float22half2_rn(make_float2(acc[2 * k] * ds, acc[2 * k + 1] * ds));
        h_out[2 * node + p] = *(uint4*)&o[0];
    }
}

// ---------------------------------------------------------------------------
// Layer 2: gather hs1 rows (32B fp16), relu, rank-1 epilogue:
//   t[n] = ds * x · wt,   wt = Wg2 @ Wo
// Pre-sync prefetch of deg/ds/indices is safe: d_p0/d_dis/d_csr were written
// >= 2 PDL hops back (agg1's griddepsync guarantees node0/fill completion).
__device__ __forceinline__ void acc_half8(float* s, uint4 u) {
    const __half2* h = (const __half2*)&u;
#pragma unroll
    for (int k = 0; k < 4; k++) {
        float2 f = __half22float2(h[k]);
        s[2 * k] += f.x; s[2 * k + 1] += f.y;
    }
}

__global__ void __launch_bounds__(256, 6)
k_agg2(const uint4* __restrict__ h_in,
       const float* __restrict__ Wg2, const float* __restrict__ bg1,
       const float* __restrict__ Wo, int n) {
    __shared__ float swt[HH], sb[HH];
    int t = threadIdx.x;
    if (t < HH) {
        float a = 0.0f;
#pragma unroll
        for (int m = 0; m < 16; m++) a = fmaf(Wg2[t * 16 + m], Wo[m], a);
        swt[t] = a;
        sb[t] = bg1[t];
    }

    int node_raw = (blockIdx.x * blockDim.x + t) >> 1;
    bool valid = node_raw < n;
    int node = valid ? node_raw : (n - 1);
    int p = t & 1;
    unsigned pmask = 3u << ((t & 31) & ~1);

    // pre-sync (safe: >= 2 hops old)
    int deg = (int)(d_p0[node] & 0xFFu);
    float ds = d_dis[node];
    const int4* cp4 = (const int4*)(d_csr + (size_t)node * CAP);
    int it4 = (deg + 3) >> 2;
    int4 pf0 = cp4[0];                 // first index group prefetch

    cudaGridDependencySynchronize();
    __syncthreads();

    float s[8];
    {   // self (h1 is 1 hop -> post-sync)
        uint4 u = h_in[2 * node + p];
        const __half2* h = (const __half2*)&u;
#pragma unroll
        for (int k = 0; k < 4; k++) {
            float2 f = __half22float2(h[k]);
            s[2 * k] = f.x; s[2 * k + 1] = f.y;
        }
    }

    int it = 0;
    for (; it + 2 <= it4; it += 2) {
        int4 ia = (it == 0) ? pf0 : cp4[it];
        int4 ib = cp4[it + 1];
        uint4 u0 = h_in[2 * ia.x + p];
        uint4 u1 = h_in[2 * ia.y + p];
        uint4 u2 = h_in[2 * ia.z + p];
        uint4 u3 = h_in[2 * ia.w + p];
        uint4 u4 = h_in[2 * ib.x + p];
        uint4 u5 = h_in[2 * ib.y + p];
        uint4 u6 = h_in[2 * ib.z + p];
        uint4 u7 = h_in[2 * ib.w + p];
        acc_half8(s, u0); acc_half8(s, u1); acc_half8(s, u2); acc_half8(s, u3);
        acc_half8(s, u4); acc_half8(s, u5); acc_half8(s, u6); acc_half8(s, u7);
    }
    if (it < it4) {
        int4 ia = (it == 0) ? pf0 : cp4[it];
        uint4 u0 = h_in[2 * ia.x + p];
        uint4 u1 = h_in[2 * ia.y + p];
        uint4 u2 = h_in[2 * ia.z + p];
        uint4 u3 = h_in[2 * ia.w + p];
        acc_half8(s, u0); acc_half8(s, u1); acc_half8(s, u2); acc_half8(s, u3);
    }
    int pads = (it4 << 2) - deg;
    if (pads > 0) {
        uint4 u = h_in[p];           // node 0 row
        const __half2* h = (const __half2*)&u;
        float f = (float)pads;
#pragma unroll
        for (int k = 0; k < 4; k++) {
            float2 v = __half22float2(h[k]);
            s[2 * k]     -= f * v.x;
            s[2 * k + 1] -= f * v.y;
        }
    }

    float tp = 0.0f;
#pragma unroll
    for (int k = 0; k < 8; k++) {
        float xk = fmaxf(fmaf(ds, s[k], sb[p * 8 + k]), 0.0f);
        tp = fmaf(xk, swt[p * 8 + k], tp);
    }
    tp *= ds;
    tp += __shfl_xor_sync(pmask, tp, 1, 2);
    if (valid && p == 0) d_t[node] = __float2half_rn(tp);
}

// ---------------------------------------------------------------------------
// Pool: gather fp16 t scalars; out[g] += (dis*(t[n]+Σt[src]) + bg2·Wo)/cnt[g].
__global__ void __launch_bounds__(256, 6)
k_pool(const int* __restrict__ batch, const float* __restrict__ bg2,
       const float* __restrict__ Wo, float* __restrict__ out, int n) {
    __shared__ float sbw;
    int t = threadIdx.x;
    if (t == 0) {
        float a = 0.0f;
#pragma unroll
        for (int k = 0; k < 16; k++) a = fmaf(bg2[k], Wo[k], a);
        sbw = a;
    }

    int node_raw = (blockIdx.x * blockDim.x + t) >> 1;
    bool valid = node_raw < n;
    int node = valid ? node_raw : (n - 1);
    int p = t & 1;
    unsigned pmask = 3u << ((t & 31) & ~1);

    // pre-sync (safe: >= 2 hops old)
    int deg = (int)(d_p0[node] & 0xFFu);
    float ds = d_dis[node];
    int g = batch[node];
    const int4* cp4 = (const int4*)(d_csr + (size_t)node * CAP);
    int it4 = (deg + 3) >> 2;

    cudaGridDependencySynchronize();
    __syncthreads();

    float sum = 0.0f;
    int it = p;
    for (; it + 2 < it4; it += 4) {
        int4 ia = cp4[it];
        int4 ib = cp4[it + 2];
        float t0 = __half2float(d_t[ia.x]), t1 = __half2float(d_t[ia.y]);
        float t2 = __half2float(d_t[ia.z]), t3 = __half2float(d_t[ia.w]);
        float t4 = __half2float(d_t[ib.x]), t5 = __half2float(d_t[ib.y]);
        float t6 = __half2float(d_t[ib.z]), t7 = __half2float(d_t[ib.w]);
        sum += (t0 + t1) + (t2 + t3) + (t4 + t5) + (t6 + t7);
    }
    for (; it < it4; it += 2) {
        int4 ia = cp4[it];
        sum += (__half2float(d_t[ia.x]) + __half2float(d_t[ia.y]))
             + (__half2float(d_t[ia.z]) + __half2float(d_t[ia.w]));
    }
    sum += __shfl_xor_sync(pmask, sum, 1, 2);

    int pads = (it4 << 2) - deg;
    if (pads > 0) sum -= (float)pads * __half2float(d_t[0]);
    sum += __half2float(d_t[node]);       // self

    float c = fmaxf(d_cnt[g], 1.0f);
    float contrib = (p == 0 && valid) ? (fmaf(ds, sum, sbw)) / c : 0.0f;

    int g0 = __shfl_sync(0xffffffffu, g, 0);
    bool uni = __all_sync(0xffffffffu, g == g0);
    if (uni) {
#pragma unroll
        for (int off = 16; off > 0; off >>= 1)
            contrib += __shfl_xor_sync(0xffffffffu, contrib, off);
        if ((t & 31) == 0) atomicAdd(&out[g0], contrib);
    } else {
        if (p == 0 && valid) atomicAdd(&out[g], contrib);
    }
}

// ---------------------------------------------------------------------------
template <typename K, typename... Args>
static inline void launch_pdl(K kernel, dim3 grid, dim3 block, Args... args) {
    cudaLaunchConfig_t cfg = {};
    cfg.gridDim = grid;
    cfg.blockDim = block;
    cfg.dynamicSmemBytes = 0;
    cfg.stream = 0;
    cudaLaunchAttribute attr[1];
    attr[0].id = cudaLaunchAttributeProgrammaticStreamSerialization;
    attr[0].val.programmaticStreamSerializationAllowed = 1;
    cfg.attrs = attr;
    cfg.numAttrs = 1;
    cudaLaunchKernelEx(&cfg, kernel, args...);
}

extern "C" void kernel_launch(void* const* d_in, const int* in_sizes, int n_in,
                              void* d_out, int out_size) {
    const int*   types = (const int*)d_in[0];
    const int*   pos   = (const int*)d_in[1];
    const int*   eidx  = (const int*)d_in[2];
    const int*   batch = (const int*)d_in[3];
    const float* W1  = (const float*)d_in[4];
    const float* b1  = (const float*)d_in[5];
    const float* W2  = (const float*)d_in[6];
    const float* b2  = (const float*)d_in[7];
    const float* Wg0 = (const float*)d_in[8];
    const float* bg0 = (const float*)d_in[9];
    const float* Wg1 = (const float*)d_in[10];
    const float* bg1 = (const float*)d_in[11];
    const float* Wg2 = (const float*)d_in[12];
    const float* bg2 = (const float*)d_in[13];
    const float* Wo  = (const float*)d_in[14];
    const float* bo  = (const float*)d_in[15];
    float* out = (float*)d_out;

    const int n = in_sizes[0];
    const int e = in_sizes[2] / 2;
    const int g = out_size;
    const int* src = eidx;
    const int* dst = eidx + e;

    uint4* h1;
    cudaGetSymbolAddress((void**)&h1, d_h1);

    const int BT = 256;
    dim3 gN((n + BT - 1) / BT);
    dim3 gP(((n * 2) + BT - 1) / BT);   // pair-per-node kernels
    int e8 = e / 8;
    dim3 gE8((e8 + BT) / BT + 1);       // covers e8 plus scalar tail threads
    dim3 bT(BT);

    launch_pdl(k_fill,  gE8, bT, src, dst, e, g);
    launch_pdl(k_node0, gN,  bT, batch, out, bo, types, pos, n, g);
    launch_pdl(k_agg1,  gP,  bT, W1, b1, W2, b2, Wg0, Wg1, bg0, h1, n);
    launch_pdl(k_agg2,  gP,  bT, (const uint4*)h1, Wg2, bg1, Wo, n);
    launch_pdl(k_pool,  gP,  bT, batch, bg2, Wo, out, n);
}

// round 16
// speedup vs baseline: 1.1376x; 1.0078x over previous
#include <cuda_runtime.h>
#include <cuda_fp16.h>
#include <stdint.h>

#define NN 100000
#define GG 1024
#define HH 16
#define CAP 128   // bucket capacity per node (mean deg 32; P(>=128) ~ 1e-30)

// Scratch (device globals; no allocation allowed)
// d_p0 packing (uint16): [0:8) capped deg | [8:12) class
__device__ unsigned short d_p0[NN];
__device__ uint4 d_h1[NN * 2];       // hs1 rows, fp16, 32B each
__device__ __half d_t[NN];           // t[n] = hs2[n]·Wo
__device__ float d_dis[NN];
__device__ float d_cnt[GG];
__device__ int   d_deg[NN];          // degree counter; re-zeroed by k_node0
__device__ int   d_csr[(size_t)NN * CAP];

// ---------------------------------------------------------------------------
// Single edge pass: count + fill buckets (8 edges/thread) + zero d_cnt.
__global__ void k_fill(const int* __restrict__ src, const int* __restrict__ dst,
                       int e, int g) {
    int i = blockIdx.x * blockDim.x + threadIdx.x;
    int e8 = e >> 3;
    bool full = (i < e8);
    int4 da, db, sa, sb;
    if (full) {                       // prefetch (overlaps predecessor tail)
        da = ((const int4*)dst)[2 * i];
        db = ((const int4*)dst)[2 * i + 1];
        sa = ((const int4*)src)[2 * i];
        sb = ((const int4*)src)[2 * i + 1];
    }
    cudaGridDependencySynchronize();
    if (i < g) d_cnt[i] = 0.0f;
    if (full) {
        int p;
        p = atomicAdd(&d_deg[da.x], 1); if (p < CAP) d_csr[(size_t)da.x * CAP + p] = sa.x;
        p = atomicAdd(&d_deg[da.y], 1); if (p < CAP) d_csr[(size_t)da.y * CAP + p] = sa.y;
        p = atomicAdd(&d_deg[da.z], 1); if (p < CAP) d_csr[(size_t)da.z * CAP + p] = sa.z;
        p = atomicAdd(&d_deg[da.w], 1); if (p < CAP) d_csr[(size_t)da.w * CAP + p] = sa.w;
        p = atomicAdd(&d_deg[db.x], 1); if (p < CAP) d_csr[(size_t)db.x * CAP + p] = sb.x;
        p = atomicAdd(&d_deg[db.y], 1); if (p < CAP) d_csr[(size_t)db.y * CAP + p] = sb.y;
        p = atomicAdd(&d_deg[db.z], 1); if (p < CAP) d_csr[(size_t)db.z * CAP + p] = sb.z;
        p = atomicAdd(&d_deg[db.w], 1); if (p < CAP) d_csr[(size_t)db.w * CAP + p] = sb.w;
    } else {
        int j = e8 * 8 + (i - e8);   // scalar tail (< 8 edges)
        if (j < e) {
            int d = dst[j];
            int p = atomicAdd(&d_deg[d], 1);
            if (p < CAP) d_csr[(size_t)d * CAP + p] = src[j];
        }
    }
}

// ---------------------------------------------------------------------------
// Node prep: dis, pad zeroing, packed (cls,deg) uint16, zero d_deg, batch
// count, out init.
__global__ void k_node0(const int* __restrict__ batch, float* __restrict__ out,
                        const float* __restrict__ bo,
                        const int* __restrict__ types, const int* __restrict__ pos,
                        int n, int g) {
    int i = blockIdx.x * blockDim.x + threadIdx.x;
    bool active = (i < n);
    if (i < g) out[i] = bo[0];       // pre-sync: out not touched by k_fill
    int cls = 0;
    if (active) cls = types[i] * 3 + pos[i];
    cudaGridDependencySynchronize();
    if (active) {
        int degraw = d_deg[i];
        float ds = rsqrtf((float)degraw + 1.0f);
        d_dis[i] = ds;
        int deg = degraw < CAP ? degraw : CAP;
        int pd = (deg + 3) & ~3;
        for (int s = deg; s < pd; s++) d_csr[(size_t)i * CAP + s] = 0;  // safe pad -> node 0
        d_p0[i] = (unsigned short)((cls << 8) | deg);
        d_deg[i] = 0;                // replaces the memset for the next call
    }
    int b = active ? batch[i] : -1;
    int b0 = __shfl_sync(0xffffffffu, b, 0);
    bool uni = __all_sync(0xffffffffu, b == b0);
    if (uni) {
        if ((threadIdx.x & 31) == 0) atomicAdd(&d_cnt[b0], 32.0f);
    } else if (active) {
        atomicAdd(&d_cnt[b], 1.0f);
    }
}

// ---------------------------------------------------------------------------
// Layer 1: gather packed (cls,deg) uint16 -> 9 class sums (dis via smem LUT)
// -> reconstruct -> relu -> matvec Wg1 -> hs1 (fp16). Lane-PAIR per node.
// 128-thread blocks.
__device__ __forceinline__ void accum9u(float* s, unsigned v, const float* sDis) {
    int cls = (int)(v >> 8);
    float dv = sDis[v & 0xFFu];
#pragma unroll
    for (int k = 0; k < 9; k++) s[k] += (cls == k) ? dv : 0.0f;
}

__global__ void __launch_bounds__(128, 12)
k_agg1(const float* __restrict__ W1, const float* __restrict__ b1,
       const float* __restrict__ W2, const float* __restrict__ b2,
       const float* __restrict__ Wg0,
       const float* __restrict__ Wg1, const float* __restrict__ bg0,
       uint4* __restrict__ h_out, int n) {
    __shared__ float sA[3][HH], sB[3][HH], sW[16 * HH], sb[HH];
    __shared__ float sDis[CAP + 1];
    int t = threadIdx.x;
    if (t < 96) {
        int which = t / 48;
        int r = (t % 48) / 16;
        int j = t % 16;
        float acc = 0.0f;
        if (which == 0) {
#pragma unroll
            for (int i = 0; i < 16; i++)
                acc = fmaf(W1[r * 16 + i] + b1[i], Wg0[i * 16 + j], acc);
            sA[r][j] = acc;
        } else {
#pragma unroll
            for (int i = 0; i < 16; i++)
                acc = fmaf(W2[r * 16 + i] + b2[i], Wg0[(16 + i) * 16 + j], acc);
            sB[r][j] = acc;
        }
    }
    sW[t] = Wg1[t];
    sW[t + 128] = Wg1[t + 128];
    if (t < HH) sb[t] = bg0[t];
    sDis[t] = rsqrtf((float)t + 1.0f);
    if (t == 0) sDis[CAP] = rsqrtf((float)CAP + 1.0f);
    cudaGridDependencySynchronize();
    __syncthreads();

    int node_raw = (blockIdx.x * blockDim.x + t) >> 1;
    bool valid = node_raw < n;
    int node = valid ? node_raw : (n - 1);
    int p = t & 1;
    unsigned pmask = 3u << ((t & 31) & ~1);

    unsigned um = d_p0[node];
    int deg = (int)(um & 0xFFu);
    float ds = d_dis[node];

    float s[9];
#pragma unroll
    for (int k = 0; k < 9; k++) s[k] = 0.0f;

    const int4* cp4 = (const int4*)(d_csr + (size_t)node * CAP);
    int it4 = (deg + 3) >> 2;
    int it = p;
    for (; it + 2 < it4; it += 4) {      // two groups (8 edges) per iteration
        int4 ia = cp4[it];
        int4 ib = cp4[it + 2];
        unsigned u0 = d_p0[ia.x], u1 = d_p0[ia.y], u2 = d_p0[ia.z], u3 = d_p0[ia.w];
        unsigned u4 = d_p0[ib.x], u5 = d_p0[ib.y], u6 = d_p0[ib.z], u7 = d_p0[ib.w];
        accum9u(s, u0, sDis); accum9u(s, u1, sDis); accum9u(s, u2, sDis); accum9u(s, u3, sDis);
        accum9u(s, u4, sDis); accum9u(s, u5, sDis); accum9u(s, u6, sDis); accum9u(s, u7, sDis);
    }
    for (; it < it4; it += 2) {
        int4 ia = cp4[it];
        unsigned u0 = d_p0[ia.x], u1 = d_p0[ia.y], u2 = d_p0[ia.z], u3 = d_p0[ia.w];
        accum9u(s, u0, sDis); accum9u(s, u1, sDis); accum9u(s, u2, sDis); accum9u(s, u3, sDis);
    }

#pragma unroll
    for (int k = 0; k < 9; k++) s[k] += __shfl_xor_sync(pmask, s[k], 1, 2);

    int pads = (it4 << 2) - deg;
    if (pads > 0) {
        unsigned u0 = d_p0[0];
        int cls0 = (int)(u0 >> 8);
        float dv0 = sDis[u0 & 0xFFu] * (float)pads;
#pragma unroll
        for (int k = 0; k < 9; k++) s[k] -= (cls0 == k) ? dv0 : 0.0f;
    }
    {
        int clsm = (int)(um >> 8);
#pragma unroll
        for (int k = 0; k < 9; k++) s[k] += (clsm == k) ? ds : 0.0f;
    }

    float u0 = s[0] + s[1] + s[2], u1 = s[3] + s[4] + s[5], u2 = s[6] + s[7] + s[8];
    float v0 = s[0] + s[3] + s[6], v1 = s[1] + s[4] + s[7], v2 = s[2] + s[5] + s[8];
    float x[16];
#pragma unroll
    for (int j = 0; j < 16; j++) {
        float agg = u0 * sA[0][j] + u1 * sA[1][j] + u2 * sA[2][j]
                  + v0 * sB[0][j] + v1 * sB[1][j] + v2 * sB[2][j];
        x[j] = fmaxf(fmaf(ds, agg, sb[j]), 0.0f);
    }

    float acc[8];
#pragma unroll
    for (int k = 0; k < 8; k++) acc[k] = 0.0f;
#pragma unroll
    for (int j = 0; j < 16; j++) {
        const float* wrow = &sW[j * 16 + p * 8];
#pragma unroll
        for (int k = 0; k < 8; k++) acc[k] = fmaf(x[j], wrow[k], acc[k]);
    }

    if (valid) {
        __half2 o[4];
#pragma unroll
        for (int k = 0; k < 4; k++)
            o[k] = __float22half2_rn(make_float2(acc[2 * k] * ds, acc[2 * k + 1] * ds));
        h_out[2 * node + p] = *(uint4*)&o[0];
    }
}

// ---------------------------------------------------------------------------
// Layer 2: gather hs1 rows (32B fp16), relu, rank-1 epilogue. Clean loop (no
// first-iteration special case). 128-thread blocks.
__device__ __forceinline__ void acc_half8(float* s, uint4 u) {
    const __half2* h = (const __half2*)&u;
#pragma unroll
    for (int k = 0; k < 4; k++) {
        float2 f = __half22float2(h[k]);
        s[2 * k] += f.x; s[2 * k + 1] += f.y;
    }
}

__global__ void __launch_bounds__(128, 12)
k_agg2(const uint4* __restrict__ h_in,
       const float* __restrict__ Wg2, const float* __restrict__ bg1,
       const float* __restrict__ Wo, int n) {
    __shared__ float swt[HH], sb[HH];
    int t = threadIdx.x;
    if (t < HH) {
        float a = 0.0f;
#pragma unroll
        for (int m = 0; m < 16; m++) a = fmaf(Wg2[t * 16 + m], Wo[m], a);
        swt[t] = a;
        sb[t] = bg1[t];
    }

    int node_raw = (blockIdx.x * blockDim.x + t) >> 1;
    bool valid = node_raw < n;
    int node = valid ? node_raw : (n - 1);
    int p = t & 1;
    unsigned pmask = 3u << ((t & 31) & ~1);

    // pre-sync scalar loads (safe: written >= 2 PDL hops back)
    int deg = (int)(d_p0[node] & 0xFFu);
    float ds = d_dis[node];
    const int4* cp4 = (const int4*)(d_csr + (size_t)node * CAP);
    int it4 = (deg + 3) >> 2;

    cudaGridDependencySynchronize();
    __syncthreads();

    float s[8];
    {   // self (h1 is 1 hop -> post-sync)
        uint4 u = h_in[2 * node + p];
        const __half2* h = (const __half2*)&u;
#pragma unroll
        for (int k = 0; k < 4; k++) {
            float2 f = __half22float2(h[k]);
            s[2 * k] = f.x; s[2 * k + 1] = f.y;
        }
    }

    int it = 0;
    for (; it + 2 <= it4; it += 2) {
        int4 ia = cp4[it];
        int4 ib = cp4[it + 1];
        uint4 u0 = h_in[2 * ia.x + p];
        uint4 u1 = h_in[2 * ia.y + p];
        uint4 u2 = h_in[2 * ia.z + p];
        uint4 u3 = h_in[2 * ia.w + p];
        uint4 u4 = h_in[2 * ib.x + p];
        uint4 u5 = h_in[2 * ib.y + p];
        uint4 u6 = h_in[2 * ib.z + p];
        uint4 u7 = h_in[2 * ib.w + p];
        acc_half8(s, u0); acc_half8(s, u1); acc_half8(s, u2); acc_half8(s, u3);
        acc_half8(s, u4); acc_half8(s, u5); acc_half8(s, u6); acc_half8(s, u7);
    }
    if (it < it4) {
        int4 ia = cp4[it];
        uint4 u0 = h_in[2 * ia.x + p];
        uint4 u1 = h_in[2 * ia.y + p];
        uint4 u2 = h_in[2 * ia.z + p];
        uint4 u3 = h_in[2 * ia.w + p];
        acc_half8(s, u0); acc_half8(s, u1); acc_half8(s, u2); acc_half8(s, u3);
    }
    int pads = (it4 << 2) - deg;
    if (pads > 0) {
        uint4 u = h_in[p];           // node 0 row
        const __half2* h = (const __half2*)&u;
        float f = (float)pads;
#pragma unroll
        for (int k = 0; k < 4; k++) {
            float2 v = __half22float2(h[k]);
            s[2 * k]     -= f * v.x;
            s[2 * k + 1] -= f * v.y;
        }
    }

    float tp = 0.0f;
#pragma unroll
    for (int k = 0; k < 8; k++) {
        float xk = fmaxf(fmaf(ds, s[k], sb[p * 8 + k]), 0.0f);
        tp = fmaf(xk, swt[p * 8 + k], tp);
    }
    tp *= ds;
    tp += __shfl_xor_sync(pmask, tp, 1, 2);
    if (valid && p == 0) d_t[node] = __float2half_rn(tp);
}

// ---------------------------------------------------------------------------
// Pool: gather fp16 t scalars; out[g] += (dis*(t[n]+Σt[src]) + bg2·Wo)/cnt[g].
// 128-thread blocks.
__global__ void __launch_bounds__(128, 12)
k_pool(const int* __restrict__ batch, const float* __restrict__ bg2,
       const float* __restrict__ Wo, float* __restrict__ out, int n) {
    __shared__ float sbw;
    int t = threadIdx.x;
    if (t == 0) {
        float a = 0.0f;
#pragma unroll
        for (int k = 0; k < 16; k++) a = fmaf(bg2[k], Wo[k], a);
        sbw = a;
    }

    int node_raw = (blockIdx.x * blockDim.x + t) >> 1;
    bool valid = node_raw < n;
    int node = valid ? node_raw : (n - 1);
    int p = t & 1;
    unsigned pmask = 3u << ((t & 31) & ~1);

    // pre-sync scalar loads (safe: >= 2 hops old)
    int deg = (int)(d_p0[node] & 0xFFu);
    float ds = d_dis[node];
    int g = batch[node];
    const int4* cp4 = (const int4*)(d_csr + (size_t)node * CAP);
    int it4 = (deg + 3) >> 2;

    cudaGridDependencySynchronize();
    __syncthreads();

    float sum = 0.0f;
    int it = p;
    for (; it + 2 < it4; it += 4) {
        int4 ia = cp4[it];
        int4 ib = cp4[it + 2];
        float t0 = __half2float(d_t[ia.x]), t1 = __half2float(d_t[ia.y]);
        float t2 = __half2float(d_t[ia.z]), t3 = __half2float(d_t[ia.w]);
        float t4 = __half2float(d_t[ib.x]), t5 = __half2float(d_t[ib.y]);
        float t6 = __half2float(d_t[ib.z]), t7 = __half2float(d_t[ib.w]);
        sum += (t0 + t1) + (t2 + t3) + (t4 + t5) + (t6 + t7);
    }
    for (; it < it4; it += 2) {
        int4 ia = cp4[it];
        sum += (__half2float(d_t[ia.x]) + __half2float(d_t[ia.y]))
             + (__half2float(d_t[ia.z]) + __half2float(d_t[ia.w]));
    }
    sum += __shfl_xor_sync(pmask, sum, 1, 2);

    int pads = (it4 << 2) - deg;
    if (pads > 0) sum -= (float)pads * __half2float(d_t[0]);
    sum += __half2float(d_t[node]);       // self

    float c = fmaxf(d_cnt[g], 1.0f);
    float contrib = (p == 0 && valid) ? (fmaf(ds, sum, sbw)) / c : 0.0f;

    int g0 = __shfl_sync(0xffffffffu, g, 0);
    bool uni = __all_sync(0xffffffffu, g == g0);
    if (uni) {
#pragma unroll
        for (int off = 16; off > 0; off >>= 1)
            contrib += __shfl_xor_sync(0xffffffffu, contrib, off);
        if ((t & 31) == 0) atomicAdd(&out[g0], contrib);
    } else {
        if (p == 0 && valid) atomicAdd(&out[g], contrib);
    }
}

// ---------------------------------------------------------------------------
template <typename K, typename... Args>
static inline void launch_pdl(K kernel, dim3 grid, dim3 block, Args... args) {
    cudaLaunchConfig_t cfg = {};
    cfg.gridDim = grid;
    cfg.blockDim = block;
    cfg.dynamicSmemBytes = 0;
    cfg.stream = 0;
    cudaLaunchAttribute attr[1];
    attr[0].id = cudaLaunchAttributeProgrammaticStreamSerialization;
    attr[0].val.programmaticStreamSerializationAllowed = 1;
    cfg.attrs = attr;
    cfg.numAttrs = 1;
    cudaLaunchKernelEx(&cfg, kernel, args...);
}

extern "C" void kernel_launch(void* const* d_in, const int* in_sizes, int n_in,
                              void* d_out, int out_size) {
    const int*   types = (const int*)d_in[0];
    const int*   pos   = (const int*)d_in[1];
    const int*   eidx  = (const int*)d_in[2];
    const int*   batch = (const int*)d_in[3];
    const float* W1  = (const float*)d_in[4];
    const float* b1  = (const float*)d_in[5];
    const float* W2  = (const float*)d_in[6];
    const float* b2  = (const float*)d_in[7];
    const float* Wg0 = (const float*)d_in[8];
    const float* bg0 = (const float*)d_in[9];
    const float* Wg1 = (const float*)d_in[10];
    const float* bg1 = (const float*)d_in[11];
    const float* Wg2 = (const float*)d_in[12];
    const float* bg2 = (const float*)d_in[13];
    const float* Wo  = (const float*)d_in[14];
    const float* bo  = (const float*)d_in[15];
    float* out = (float*)d_out;

    const int n = in_sizes[0];
    const int e = in_sizes[2] / 2;
    const int g = out_size;
    const int* src = eidx;
    const int* dst = eidx + e;

    uint4* h1;
    cudaGetSymbolAddress((void**)&h1, d_h1);

    dim3 gN((n + 255) / 256), bN(256);
    dim3 gP(((n * 2) + 127) / 128), bP(128);   // pair-per-node kernels
    int e8 = e / 8;
    dim3 gE8((e8 + 256) / 256 + 1), bE(256);

    launch_pdl(k_fill,  gE8, bE, src, dst, e, g);
    launch_pdl(k_node0, gN,  bN, batch, out, bo, types, pos, n, g);
    launch_pdl(k_agg1,  gP,  bP, W1, b1, W2, b2, Wg0, Wg1, bg0, h1, n);
    launch_pdl(k_agg2,  gP,  bP, (const uint4*)h1, Wg2, bg1, Wo, n);
    launch_pdl(k_pool,  gP,  bP, batch, bg2, Wo, out, n);
}